// round 10
// baseline (speedup 1.0000x reference)
#include <cuda_runtime.h>
#include <math.h>

typedef unsigned long long u64;

#define NG 8
#define NT 2048
#define NH 2048
#define NE 8
#define CAP 320
#define NTOK (NG * NT)        // 16384
#define TPBK 64               // tokens per block
#define NBLK (NTOK / TPBK)    // 256
#define BPG (NBLK / NG)       // 32 blocks per group
#define THREADS 512
#define NITER 16              // H chunks of 128 floats
#define ROWB 528              // stage row bytes/token (132 words: 16B-aligned, odd/4 -> conflict-free)
#define STAGEB (TPBK * ROWB)  // 33792 B per stage
#define NSTAGE 3
#define SMEM_W 65536
#define SMEM_TOTAL (SMEM_W + NSTAGE * STAGEB + TPBK * 9 * 4 + 8 * 4 + TPBK * 4)

// scratch: argmax ids; per-group completion counters.
// g_cnt is tested modulo BPG -> never needs resetting across graph replays.
__device__ unsigned char g_expert_id[NTOK];
__device__ unsigned int  g_cnt[NG];

__device__ __forceinline__ void fma2(u64& acc, u64 a, u64 b) {
    asm("fma.rn.f32x2 %0, %1, %2, %0;" : "+l"(acc) : "l"(a), "l"(b));
}
__device__ __forceinline__ u64 add2(u64 a, u64 b) {
    u64 r; asm("add.rn.f32x2 %0, %1, %2;" : "=l"(r) : "l"(a), "l"(b));
    return r;
}
__device__ __forceinline__ u64 pack2(float lo, float hi) {
    u64 r; asm("mov.b64 %0, {%1, %2};" : "=l"(r) : "f"(lo), "f"(hi));
    return r;
}
__device__ __forceinline__ u64 dup2(float v) { return pack2(v, v); }
__device__ __forceinline__ void unpack2(u64 v, float& lo, float& hi) {
    asm("mov.b64 {%0, %1}, %2;" : "=f"(lo), "=f"(hi) : "l"(v));
}
__device__ __forceinline__ void cp16(unsigned dst, const void* src) {
    asm volatile("cp.async.cg.shared.global [%0], [%1], 16;"
                 :: "r"(dst), "l"(src) : "memory");
}
#define CP_COMMIT() asm volatile("cp.async.commit_group;" ::: "memory")
#define CP_WAIT1()  asm volatile("cp.async.wait_group 1;"  ::: "memory")
#define CP_WAIT0()  asm volatile("cp.async.wait_group 0;"  ::: "memory")

// ---------------------------------------------------------------------------
// Capacity epilogue (512-thread block; first 256 threads do the scan work).
// Per-group inclusive cumsum of assignments; zero over-capacity one-hots.
// ---------------------------------------------------------------------------
__device__ void capacity_epilogue(int g, float* __restrict__ out) {
    const int tid = threadIdx.x;
    const int lane = tid & 31, wrp = tid >> 5;
    __shared__ int wt[8][NE];

    u64 ids = 0;
    int c[NE], s[NE];
#pragma unroll
    for (int e = 0; e < NE; e++) { c[e] = 0; s[e] = 0; }

    if (tid < 256) {
        ids = ((const u64*)g_expert_id)[g * (NT / 8) + tid];
#pragma unroll
        for (int i = 0; i < 8; i++) {
            int e = (int)((ids >> (8 * i)) & 0xFFULL);
#pragma unroll
            for (int ee = 0; ee < NE; ee++) c[ee] += (e == ee);
        }
#pragma unroll
        for (int e = 0; e < NE; e++) s[e] = c[e];
#pragma unroll
        for (int off = 1; off < 32; off <<= 1) {
#pragma unroll
            for (int e = 0; e < NE; e++) {
                int v = __shfl_up_sync(0xffffffffu, s[e], off);
                if (lane >= off) s[e] += v;
            }
        }
        if (lane == 31) {
#pragma unroll
            for (int e = 0; e < NE; e++) wt[wrp][e] = s[e];
        }
    }
    __syncthreads();
    if (tid < NE) {            // exclusive scan of 8 warp totals
        int run = 0;
#pragma unroll
        for (int w = 0; w < 8; w++) {
            int v = wt[w][tid];
            wt[w][tid] = run;
            run += v;
        }
    }
    __syncthreads();

    if (tid < 256) {
        int base[NE];
#pragma unroll
        for (int e = 0; e < NE; e++) base[e] = (s[e] - c[e]) + wt[wrp][e];

        int run2[NE];
#pragma unroll
        for (int e = 0; e < NE; e++) run2[e] = 0;

        const size_t tok0 = (size_t)g * NT + (size_t)tid * 8;
#pragma unroll
        for (int i = 0; i < 8; i++) {
            int e = (int)((ids >> (8 * i)) & 0xFFULL);
#pragma unroll
            for (int ee = 0; ee < NE; ee++) {
                int inc = (e == ee);
                run2[ee] += inc;
                if (inc && (base[ee] + run2[ee] > CAP))
                    out[(tok0 + i) * NE + ee] = 0.0f;
            }
        }
    }
}

// ---------------------------------------------------------------------------
// Router kernel. cp.async 3-stage pipeline stages x through smem (loads are
// register-free -> DRAM stays saturated during compute). Compute: lane=token,
// warp w owns h-slice [w*8, w*8+8) of each 128-h chunk; each lane handles
// tokens (lane) and (lane+32). W reads are smem broadcasts. Per-warp partial
// logits reduced at the end via a buffer aliased onto a retired stage.
// ---------------------------------------------------------------------------
__global__ __launch_bounds__(THREADS, 1)
void router_kernel(const float* __restrict__ hs,
                   const float* __restrict__ W,
                   const float* __restrict__ bias,
                   float* __restrict__ out) {
    extern __shared__ char smem[];
    u64*   shw      = (u64*)smem;                            // W: 64 KB
    char*  stages   = smem + SMEM_W;                         // 3 x 33792
    float* sh_logit = (float*)(smem + SMEM_W + NSTAGE * STAGEB);
    float* sh_bias  = sh_logit + TPBK * 9;
    int*   sh_arg   = (int*)(sh_bias + 8);

    const int tid  = threadIdx.x;
    const int lane = tid & 31, warp = tid >> 5;
    const unsigned smem_u = (unsigned)__cvta_generic_to_shared(smem);

    // W fill: shwf[h*8 + p*2 + half] = W[2p+half][h]  (broadcast layout)
    {
        float* shwf = (float*)shw;
        const float4* W4 = (const float4*)W;
#pragma unroll
        for (int q = 0; q < 8; q++) {
            int idx4 = tid + q * THREADS;            // 0..4095
            float4 v = W4[idx4];
#pragma unroll
            for (int c = 0; c < 4; c++) {
                int f = idx4 * 4 + c;                // e*2048 + h
                int e = f >> 11, h = f & 2047;
                float val = (c == 0) ? v.x : (c == 1) ? v.y
                          : (c == 2) ? v.z : v.w;
                shwf[h * 8 + (e >> 1) * 2 + (e & 1)] = val;
            }
        }
    }
    if (tid < 8) sh_bias[tid] = bias[tid];

    const size_t gtok0 = (size_t)blockIdx.x * TPBK;

    // stage issue: thread copies 4x16B; idx -> (token t, 16B-chunk c4)
    auto issue = [&](int i) {
        unsigned base = smem_u + SMEM_W + (unsigned)((i % NSTAGE) * STAGEB);
#pragma unroll
        for (int k = 0; k < 4; k++) {
            int idx = tid + k * THREADS;             // 0..2047
            int t = idx >> 5, c4 = idx & 31;
            const float* src = hs + (gtok0 + t) * NH + i * 128 + c4 * 4;
            cp16(base + t * ROWB + c4 * 16, src);
        }
        CP_COMMIT();
    };

    issue(0);
    issue(1);

    u64 acc[2][4];
#pragma unroll
    for (int t = 0; t < 2; t++)
#pragma unroll
        for (int p = 0; p < 4; p++) acc[t][p] = 0ULL;

    const int t1 = lane, t2 = lane + 32;

    // compute one 128-h chunk from a stage buffer
    auto compute = [&](int i) {
        const char* st = stages + (i % NSTAGE) * STAGEB;
        const float4* x1 = (const float4*)(st + t1 * ROWB + warp * 32);
        const float4* x2 = (const float4*)(st + t2 * ROWB + warp * 32);
        float4 xa = x1[0], xb = x1[1];               // token t1, h j=0..7
        float4 xc = x2[0], xd = x2[1];               // token t2
        const u64* wb = shw + (size_t)(i * 128 + warp * 8) * 4;
#pragma unroll
        for (int j = 0; j < 8; j++) {
            u64 w0 = wb[j * 4 + 0];
            u64 w1 = wb[j * 4 + 1];
            u64 w2 = wb[j * 4 + 2];
            u64 w3 = wb[j * 4 + 3];
            float xs1 = (j == 0) ? xa.x : (j == 1) ? xa.y : (j == 2) ? xa.z
                      : (j == 3) ? xa.w : (j == 4) ? xb.x : (j == 5) ? xb.y
                      : (j == 6) ? xb.z : xb.w;
            float xs2 = (j == 0) ? xc.x : (j == 1) ? xc.y : (j == 2) ? xc.z
                      : (j == 3) ? xc.w : (j == 4) ? xd.x : (j == 5) ? xd.y
                      : (j == 6) ? xd.z : xd.w;
            u64 d1 = dup2(xs1), d2 = dup2(xs2);
            fma2(acc[0][0], d1, w0);  fma2(acc[1][0], d2, w0);
            fma2(acc[0][1], d1, w1);  fma2(acc[1][1], d2, w1);
            fma2(acc[0][2], d1, w2);  fma2(acc[1][2], d2, w2);
            fma2(acc[0][3], d1, w3);  fma2(acc[1][3], d2, w3);
        }
    };

#pragma unroll 1
    for (int i = 0; i < NITER - 1; i++) {
        CP_WAIT1();            // stage i arrived (i, i+1 outstanding)
        __syncthreads();       // visible to all; all done consuming slot (i-1)%3
        if (i + 2 < NITER) issue(i + 2);   // slot (i-1)%3, now free
        compute(i);
    }
    CP_WAIT0();
    __syncthreads();
    compute(NITER - 1);

    // per-warp partial logits -> smem (aliased onto retired stage slot 1:
    // last read at i=13; all warps passed the i=14 barrier, so it is free).
    {
        u64* part = (u64*)(stages + 1 * STAGEB);
#pragma unroll
        for (int t = 0; t < 2; t++)
#pragma unroll
            for (int p = 0; p < 4; p++)
                part[warp * (TPBK * 4) + (lane + t * 32) * 4 + p] = acc[t][p];
    }
    __syncthreads();

    // reduce 16 warp-partials per (token, expert-pair); 256 threads
    if (tid < TPBK * 4) {
        const u64* part = (const u64*)(stages + 1 * STAGEB);
        int t = tid >> 2, p = tid & 3;
        u64 s = part[t * 4 + p];
#pragma unroll
        for (int w = 1; w < 16; w++)
            s = add2(s, part[w * (TPBK * 4) + t * 4 + p]);
        float lo, hi;
        unpack2(s, lo, hi);
        sh_logit[t * 9 + 2 * p]     = lo + sh_bias[2 * p];
        sh_logit[t * 9 + 2 * p + 1] = hi + sh_bias[2 * p + 1];
    }
    __syncthreads();

    // softmax stats + argmax (first-max semantics matches jnp.argmax)
    if (tid < TPBK) {
        const float* l = sh_logit + tid * 9;
        float best = l[0]; int bi = 0;
#pragma unroll
        for (int e = 1; e < NE; e++) {
            float v = l[e];
            if (v > best) { best = v; bi = e; }
        }
        float ssum = 0.f;
#pragma unroll
        for (int e = 0; e < NE; e++) ssum += expf(l[e] - best);
        sh_arg[tid] = bi;
        int gt = blockIdx.x * TPBK + tid;
        out[(size_t)NTOK * NE + gt] = 1.0f / ssum;   // max router prob
        g_expert_id[gt] = (unsigned char)bi;
    }
    __syncthreads();

    // one-hot (pre-capacity) + logits: 512 threads = (64 tokens x 8 experts)
    {
        int t = tid >> 3, e = tid & 7;
        int gt = blockIdx.x * TPBK + t;
        out[(size_t)gt * NE + e] = (e == sh_arg[t]) ? 1.0f : 0.0f;
        out[(size_t)NTOK * NE + NTOK + (size_t)gt * NE + e] = sh_logit[t * 9 + e];
    }

    // ---- fused capacity epilogue: last block of each group runs it ----
    __threadfence();
    __syncthreads();
    __shared__ int s_last;
    if (tid == 0) {
        unsigned int v = atomicAdd(&g_cnt[blockIdx.x / BPG], 1u);
        s_last = ((v & (BPG - 1)) == (BPG - 1));
    }
    __syncthreads();
    if (s_last) {
        __threadfence();   // acquire: see all group blocks' writes
        capacity_epilogue(blockIdx.x / BPG, out);
    }
}

// ---------------------------------------------------------------------------
extern "C" void kernel_launch(void* const* d_in, const int* in_sizes, int n_in,
                              void* d_out, int out_size) {
    const float* hs = (const float*)d_in[0];   // [8, 2048, 2048] f32
    const float* W  = (const float*)d_in[1];   // [8, 2048] f32
    const float* b  = (const float*)d_in[2];   // [8] f32
    float* out = (float*)d_out;

    cudaFuncSetAttribute(router_kernel,
                         cudaFuncAttributeMaxDynamicSharedMemorySize, SMEM_TOTAL);

    router_kernel<<<NBLK, THREADS, SMEM_TOTAL>>>(hs, W, b, out);
}